// round 15
// baseline (speedup 1.0000x reference)
#include <cuda_runtime.h>
#include <cuda_fp16.h>

#define N_NODES 50000
#define N_EDGES 800000
#define D 64
#define SCAN_BLKS 196                     // 196*256 = 50176 >= N_NODES
#define GEMM_BLKS ((N_NODES + 63) / 64)   // 782 (64 rows per block)
#define FILL_BLKS ((N_EDGES / 4 + 255) / 256)  // 782

// Scratch (device globals: allocation-free; zero-initialized at module load).
// INVARIANT: g_degi is all-zero at entry of every kernel_launch call:
//   k_count builds it, the fill path drains it back to zero.
__device__ __half g_xh[N_NODES * D];     // xs = (x@W)*dis[row], fp16 (row = 128B)
__device__ float  g_dis[N_NODES];
__device__ int    g_degi[N_NODES];       // edge-only in-degree (drained by fill)
__device__ int    g_off[N_NODES + 1];    // CSR offsets (exclusive scan, +total)
__device__ int    g_srcs[N_EDGES];       // CSR src lists grouped by dst
__device__ int    g_part[SCAN_BLKS];     // per-block partial sums
__device__ int    g_pbase[SCAN_BLKS];    // exclusive base per block

// ---------------------------------------------------------------------------
// K1: count in-degrees. 4 edges per thread via int4.
__global__ void __launch_bounds__(256) k_count(const int* __restrict__ ei) {
    int t = blockIdx.x * 256 + threadIdx.x;
    if (t < N_EDGES / 4) {
        int4 d = __ldg(reinterpret_cast<const int4*>(ei + N_EDGES) + t);
        atomicAdd(&g_degi[d.x], 1);
        atomicAdd(&g_degi[d.y], 1);
        atomicAdd(&g_degi[d.z], 1);
        atomicAdd(&g_degi[d.w], 1);
    }
}

// K2a: per-block partial sums of g_degi (coalesced)
__global__ void __launch_bounds__(256) k_scanA() {
    int idx = blockIdx.x * 256 + threadIdx.x;
    int v = (idx < N_NODES) ? g_degi[idx] : 0;
    #pragma unroll
    for (int o = 16; o > 0; o >>= 1) v += __shfl_down_sync(~0u, v, o);
    __shared__ int ws[8];
    int lane = threadIdx.x & 31, wid = threadIdx.x >> 5;
    if (lane == 0) ws[wid] = v;
    __syncthreads();
    if (threadIdx.x == 0) {
        int s = 0;
        #pragma unroll
        for (int k = 0; k < 8; k++) s += ws[k];
        g_part[blockIdx.x] = s;
    }
}

// K2b: scan the SCAN_BLKS partials (1 block)
__global__ void __launch_bounds__(256) k_scanB() {
    __shared__ int sp[256];
    int t = threadIdx.x;
    int v = (t < SCAN_BLKS) ? g_part[t] : 0;
    sp[t] = v;
    __syncthreads();
    for (int o = 1; o < 256; o <<= 1) {
        int n = 0;
        if (t >= o) n = sp[t - o];
        __syncthreads();
        sp[t] += n;
        __syncthreads();
    }
    if (t < SCAN_BLKS) g_pbase[t] = sp[t] - v;      // exclusive
    if (t == 255) g_off[N_NODES] = sp[255];         // total = N_EDGES
}

// K2c: final offsets + dis = rsqrt(deg+1) (coalesced, block-local excl scan)
__global__ void __launch_bounds__(256) k_scanC() {
    int idx = blockIdx.x * 256 + threadIdx.x;
    int t = threadIdx.x, lane = t & 31, wid = t >> 5;
    int v = (idx < N_NODES) ? g_degi[idx] : 0;

    int inc = v;
    #pragma unroll
    for (int o = 1; o < 32; o <<= 1) {
        int n = __shfl_up_sync(~0u, inc, o);
        if (lane >= o) inc += n;
    }
    __shared__ int ws[8];
    if (lane == 31) ws[wid] = inc;
    __syncthreads();
    if (t == 0) {
        int run = 0;
        #pragma unroll
        for (int k = 0; k < 8; k++) { int tmp = ws[k]; ws[k] = run; run += tmp; }
    }
    __syncthreads();
    int excl = inc - v + ws[wid] + g_pbase[blockIdx.x];

    if (idx < N_NODES) {
        g_off[idx] = excl;
        g_dis[idx] = rsqrtf((float)(v + 1));        // +1 self loop
    }
}

// K3: FUSED gemm+fill. Blocks [0,GEMM_BLKS) do xs=(x@W)*dis (fp16 out);
// blocks [GEMM_BLKS, GEMM_BLKS+FILL_BLKS) do CSR bucket-fill (drains g_degi).
// Both depend only on scanC; fusing gives SM-level overlap without streams.
#define XS 68                             // padded row stride (floats)
__global__ void __launch_bounds__(256) k_gemm_fill(const float* __restrict__ x,
                                                   const float* __restrict__ W,
                                                   const int* __restrict__ ei) {
    __shared__ float sW[D * D];
    __shared__ float sx[64 * XS];

    if (blockIdx.x >= GEMM_BLKS) {
        // ---- fill path ----
        int t = (blockIdx.x - GEMM_BLKS) * 256 + threadIdx.x;
        if (t < N_EDGES / 4) {
            int4 s = __ldg(reinterpret_cast<const int4*>(ei) + t);
            int4 d = __ldg(reinterpret_cast<const int4*>(ei + N_EDGES) + t);
            int o0 = g_off[d.x], o1 = g_off[d.y], o2 = g_off[d.z], o3 = g_off[d.w];
            int c0 = atomicAdd(&g_degi[d.x], -1);
            int c1 = atomicAdd(&g_degi[d.y], -1);
            int c2 = atomicAdd(&g_degi[d.z], -1);
            int c3 = atomicAdd(&g_degi[d.w], -1);
            g_srcs[o0 + c0 - 1] = s.x;
            g_srcs[o1 + c1 - 1] = s.y;
            g_srcs[o2 + c2 - 1] = s.z;
            g_srcs[o3 + c3 - 1] = s.w;
        }
        return;
    }

    // ---- gemm path: 64 rows per block, thread = 1 row x 16 cols ----
    float4* sW4 = reinterpret_cast<float4*>(sW);
    float4* sx4 = reinterpret_cast<float4*>(sx);
    const int tid = threadIdx.x;
    const int row0 = blockIdx.x * 64;

    #pragma unroll
    for (int i = tid; i < D * D / 4; i += 256)
        sW4[i] = reinterpret_cast<const float4*>(W)[i];
    #pragma unroll
    for (int i = tid; i < 64 * 16; i += 256) {
        int r = i >> 4;
        int c = i & 15;
        int gr = row0 + r;
        sx4[r * (XS / 4) + c] = (gr < N_NODES)
            ? __ldg(reinterpret_cast<const float4*>(x) + (size_t)gr * 16 + c)
            : make_float4(0.f, 0.f, 0.f, 0.f);
    }
    __syncthreads();

    const int r  = tid >> 2;          // 0..63
    const int cg = tid & 3;           // 16-col group
    const float* xr = sx + r * XS;

    float4 a0, a1, a2, a3;
    a0 = a1 = a2 = a3 = make_float4(0.f, 0.f, 0.f, 0.f);

    #pragma unroll 8
    for (int k = 0; k < D; k++) {
        float4 w0 = sW4[k * 16 + cg * 4 + 0];
        float4 w1 = sW4[k * 16 + cg * 4 + 1];
        float4 w2 = sW4[k * 16 + cg * 4 + 2];
        float4 w3 = sW4[k * 16 + cg * 4 + 3];
        float xv = xr[k];
        a0.x += xv * w0.x; a0.y += xv * w0.y; a0.z += xv * w0.z; a0.w += xv * w0.w;
        a1.x += xv * w1.x; a1.y += xv * w1.y; a1.z += xv * w1.z; a1.w += xv * w1.w;
        a2.x += xv * w2.x; a2.y += xv * w2.y; a2.z += xv * w2.z; a2.w += xv * w2.w;
        a3.x += xv * w3.x; a3.y += xv * w3.y; a3.z += xv * w3.z; a3.w += xv * w3.w;
    }

    const int gr = row0 + r;
    if (gr < N_NODES) {
        float dis = g_dis[gr];
        __half2 h[8];
        h[0] = __floats2half2_rn(a0.x * dis, a0.y * dis);
        h[1] = __floats2half2_rn(a0.z * dis, a0.w * dis);
        h[2] = __floats2half2_rn(a1.x * dis, a1.y * dis);
        h[3] = __floats2half2_rn(a1.z * dis, a1.w * dis);
        h[4] = __floats2half2_rn(a2.x * dis, a2.y * dis);
        h[5] = __floats2half2_rn(a2.z * dis, a2.w * dis);
        h[6] = __floats2half2_rn(a3.x * dis, a3.y * dis);
        h[7] = __floats2half2_rn(a3.z * dis, a3.w * dis);
        uint4* dst = reinterpret_cast<uint4*>(g_xh + (size_t)gr * D) + cg * 2;
        dst[0] = *reinterpret_cast<uint4*>(&h[0]);
        dst[1] = *reinterpret_cast<uint4*>(&h[4]);
    }
}

// K5: gather. One warp per node (uniform control); lane owns one half2 (2 cols).
// One edge gather = 32 lanes x 4B = one 128B line.
// out[i] = dis[i] * (xs[i] + sum_j xs[src_j]) + b
__global__ void __launch_bounds__(256) k_gather(const float* __restrict__ b,
                                                float* __restrict__ out) {
    int warp = (blockIdx.x * 256 + threadIdx.x) >> 5;
    int lane = threadIdx.x & 31;
    if (warp >= N_NODES) return;
    const int i = warp;

    const __half2* xh = reinterpret_cast<const __half2*>(g_xh);
    const int col = i * 32 + lane;

    float2 acc = __half22float2(__ldg(&xh[col]));   // self term xs[i]
    int j = __ldg(&g_off[i]);
    const int end = __ldg(&g_off[i + 1]);

    for (; j + 8 <= end; j += 8) {                  // MLP = 8
        int s0 = __ldg(&g_srcs[j + 0]);
        int s1 = __ldg(&g_srcs[j + 1]);
        int s2 = __ldg(&g_srcs[j + 2]);
        int s3 = __ldg(&g_srcs[j + 3]);
        int s4 = __ldg(&g_srcs[j + 4]);
        int s5 = __ldg(&g_srcs[j + 5]);
        int s6 = __ldg(&g_srcs[j + 6]);
        int s7 = __ldg(&g_srcs[j + 7]);
        float2 v0 = __half22float2(__ldg(&xh[s0 * 32 + lane]));
        float2 v1 = __half22float2(__ldg(&xh[s1 * 32 + lane]));
        float2 v2 = __half22float2(__ldg(&xh[s2 * 32 + lane]));
        float2 v3 = __half22float2(__ldg(&xh[s3 * 32 + lane]));
        float2 v4 = __half22float2(__ldg(&xh[s4 * 32 + lane]));
        float2 v5 = __half22float2(__ldg(&xh[s5 * 32 + lane]));
        float2 v6 = __half22float2(__ldg(&xh[s6 * 32 + lane]));
        float2 v7 = __half22float2(__ldg(&xh[s7 * 32 + lane]));
        acc.x += ((v0.x + v1.x) + (v2.x + v3.x)) + ((v4.x + v5.x) + (v6.x + v7.x));
        acc.y += ((v0.y + v1.y) + (v2.y + v3.y)) + ((v4.y + v5.y) + (v6.y + v7.y));
    }
    for (; j < end; j++) {
        int s = __ldg(&g_srcs[j]);
        float2 v = __half22float2(__ldg(&xh[s * 32 + lane]));
        acc.x += v.x;
        acc.y += v.y;
    }

    float dis = __ldg(&g_dis[i]);
    float2 bb = __ldg(reinterpret_cast<const float2*>(b) + lane);
    float2 o;
    o.x = acc.x * dis + bb.x;
    o.y = acc.y * dis + bb.y;
    reinterpret_cast<float2*>(out)[col] = o;
}

extern "C" void kernel_launch(void* const* d_in, const int* in_sizes, int n_in,
                              void* d_out, int out_size) {
    const float* x  = (const float*)d_in[0];
    const int*   ei = (const int*)d_in[1];     // int64 in reference, delivered as int32
    const float* W  = (const float*)d_in[2];
    const float* b  = (const float*)d_in[3];
    float* out = (float*)d_out;

    (void)in_sizes; (void)n_in; (void)out_size;

    k_count    <<<(N_EDGES / 4 + 255) / 256, 256>>>(ei);
    k_scanA    <<<SCAN_BLKS, 256>>>();
    k_scanB    <<<1, 256>>>();
    k_scanC    <<<SCAN_BLKS, 256>>>();
    k_gemm_fill<<<GEMM_BLKS + FILL_BLKS, 256>>>(x, W, ei);
    k_gather   <<<(N_NODES * 32 + 255) / 256, 256>>>(b, out);
}